// round 9
// baseline (speedup 1.0000x reference)
#include <cuda_runtime.h>
#include <cuda_fp16.h>
#include <math.h>
#include <stdint.h>

#define BATCH 4
#define CCH   512
#define NSP   4096

// ---------------- scratch (static device globals; allocation-free) ----------------
__device__ unsigned short gh_hnT [(size_t)BATCH * NSP * CCH];        // [b][n][c] fp16
__device__ unsigned short gh_qkT [(size_t)BATCH * NSP * 2 * CCH];    // [b][n][0:512 q | 512:1024 k]
__device__ unsigned short gh_v   [(size_t)BATCH * CCH * NSP];        // [b][c][n]
__device__ unsigned short gh_oT  [(size_t)BATCH * NSP * CCH];        // [b][n][c]
__device__ unsigned short gh_w   [(size_t)4 * CCH * CCH];            // wq,wk,wv,wo fp16
__device__ unsigned short gh_attn[(size_t)BATCH * NSP * NSP];        // fp16 exp-scores
__device__ float g_ga[BATCH * CCH];
__device__ float g_be[BATCH * CCH];
__device__ float g_bqk[2 * CCH];
__device__ float g_rinv[(size_t)BATCH * NSP];                        // 1/rowsum

// ---------------- helpers ----------------
__device__ __forceinline__ void cpa16(void* dst, const void* src){
    uint32_t s = (uint32_t)__cvta_generic_to_shared(dst);
    asm volatile("cp.async.cg.shared.global [%0], [%1], 16;" :: "r"(s), "l"(src));
}
#define CP_COMMIT() asm volatile("cp.async.commit_group;")

__device__ __forceinline__ void ldm_x4(uint32_t* r, const void* p){
    uint32_t a = (uint32_t)__cvta_generic_to_shared(p);
    asm volatile("ldmatrix.sync.aligned.m8n8.x4.shared.b16 {%0,%1,%2,%3}, [%4];"
        : "=r"(r[0]), "=r"(r[1]), "=r"(r[2]), "=r"(r[3]) : "r"(a));
}

__device__ __forceinline__ void mma16(float* c, const uint32_t* a, const uint32_t* b){
    asm volatile(
      "mma.sync.aligned.m16n8k16.row.col.f32.f16.f16.f32 "
      "{%0,%1,%2,%3},{%4,%5,%6,%7},{%8,%9},{%0,%1,%2,%3};"
      : "+f"(c[0]), "+f"(c[1]), "+f"(c[2]), "+f"(c[3])
      : "r"(a[0]), "r"(a[1]), "r"(a[2]), "r"(a[3]), "r"(b[0]), "r"(b[1]));
}

__device__ __forceinline__ uint32_t pack2(float x, float y){
    __half2 h = __floats2half2_rn(x, y);
    return *reinterpret_cast<uint32_t*>(&h);
}

// XOR-swizzled offset within a 128-row x 64-half tile (row stride 128 B).
__device__ __forceinline__ int swz(int r, int c){
    return r * 64 + ((((c >> 3) ^ (r & 7)) & 7) << 3) + (c & 7);
}

// ============================ fp16 tensor-core GEMM ============================
// BM=128, BN=128, BK=64, 256 threads, warp grid 2(M) x 4(N), warp tile 64x32.
// 3-stage cp.async pipeline, XOR swizzle, ONE __syncthreads per iteration.
// D[m][n] = scale * sum_k A[m][k] * B[n][k]  (+bias)
// rowscale: optional per-row fp32 multiplier (applied after bias), stride M per batch.
// do_exp: apply __expf at the end (for fused softmax numerator).
#define TILE_H (128 * 64)
#define BUF_H  (2 * TILE_H)
#define SMEM_BYTES (3 * BUF_H * 2)        // 98304 B

__global__ void __launch_bounds__(256, 2) hgemm(
    const __half* __restrict__ A, const __half* __restrict__ B,
    const float* __restrict__ bias, const float* __restrict__ res,
    const float* __restrict__ rowscale,
    void* __restrict__ D,
    int K, int ldA, int ldB, int ldD,
    size_t sA, size_t sB, size_t sD,
    float scale, int bias_col, int out_f32, int do_exp)
{
    extern __shared__ __half smh[];

    const int tid = threadIdx.x, lane = tid & 31, wid = tid >> 5;
    const int g = lane >> 2, tig = lane & 3;
    const int wm = wid >> 2, wn = wid & 3;
    const int m0 = blockIdx.y * 128, n0 = blockIdx.x * 128;
    const int bz = blockIdx.z;

    const __half* Ag = A + (size_t)bz * sA;
    const __half* Bg = B + (size_t)bz * sB;
    const float* rsp = rowscale ? rowscale + (size_t)bz * (gridDim.y * 128) : nullptr;

    float acc[4][4][4];
    #pragma unroll
    for (int i = 0; i < 4; i++)
        #pragma unroll
        for (int j = 0; j < 4; j++)
            #pragma unroll
            for (int r = 0; r < 4; r++) acc[i][j][r] = 0.f;

    const int NK = K >> 6;

    auto stage = [&](int ks){
        __half* Asm = smh + (ks % 3) * BUF_H;
        __half* Bsm = Asm + TILE_H;
        #pragma unroll
        for (int it = 0; it < 4; it++){
            const int idx = it * 256 + tid;
            const int r = idx >> 3, c = (idx & 7) * 8;
            const int so = swz(r, c);
            cpa16(Asm + so, Ag + (size_t)(m0 + r) * ldA + ks * 64 + c);
            cpa16(Bsm + so, Bg + (size_t)(n0 + r) * ldB + ks * 64 + c);
        }
        CP_COMMIT();
    };

    stage(0);
    if (NK > 1) stage(1);

    const int a_row  = (lane & 15);
    const int a_koff = (lane >> 4) * 8;
    const int b_row  = ((lane >> 4) << 3) + (lane & 7);
    const int b_koff = ((lane >> 3) & 1) * 8;

    for (int ks = 0; ks < NK; ks++){
        if (ks + 1 < NK) { asm volatile("cp.async.wait_group 1;"); }
        else             { asm volatile("cp.async.wait_group 0;"); }
        __syncthreads();

        const __half* Asm = smh + (ks % 3) * BUF_H;
        const __half* Bsm = Asm + TILE_H;

        #pragma unroll
        for (int kk = 0; kk < 64; kk += 16){
            uint32_t a[4][4], b[4][2];
            #pragma unroll
            for (int mi = 0; mi < 4; mi++)
                ldm_x4(a[mi], Asm + swz(wm*64 + mi*16 + a_row, kk + a_koff));
            #pragma unroll
            for (int pj = 0; pj < 2; pj++){
                uint32_t t4[4];
                ldm_x4(t4, Bsm + swz(wn*32 + pj*16 + b_row, kk + b_koff));
                b[2*pj  ][0] = t4[0]; b[2*pj  ][1] = t4[1];
                b[2*pj+1][0] = t4[2]; b[2*pj+1][1] = t4[3];
            }
            #pragma unroll
            for (int mi = 0; mi < 4; mi++)
                #pragma unroll
                for (int nj = 0; nj < 4; nj++)
                    mma16(acc[mi][nj], a[mi], b[nj]);
        }

        if (ks + 2 < NK) stage(ks + 2);
    }

    // ---------------- epilogue ----------------
    #pragma unroll
    for (int mi = 0; mi < 4; mi++){
        const int r0 = m0 + wm * 64 + mi * 16 + g;
        float br0 = 0.f, br1 = 0.f;
        if (bias && !bias_col){ br0 = bias[r0]; br1 = bias[r0 + 8]; }
        float rs0 = 1.f, rs1 = 1.f;
        if (rsp){ rs0 = rsp[r0]; rs1 = rsp[r0 + 8]; }
        #pragma unroll
        for (int nj = 0; nj < 4; nj++){
            const int col = n0 + wn * 32 + nj * 8 + tig * 2;
            float v0 = acc[mi][nj][0] * scale;
            float v1 = acc[mi][nj][1] * scale;
            float v2 = acc[mi][nj][2] * scale;
            float v3 = acc[mi][nj][3] * scale;
            if (bias){
                if (bias_col){
                    const float bc0 = bias[col], bc1 = bias[col + 1];
                    v0 += bc0; v1 += bc1; v2 += bc0; v3 += bc1;
                } else {
                    v0 += br0; v1 += br0; v2 += br1; v3 += br1;
                }
            }
            if (rsp){ v0 *= rs0; v1 *= rs0; v2 *= rs1; v3 *= rs1; }
            if (do_exp){
                v0 = __expf(v0); v1 = __expf(v1);
                v2 = __expf(v2); v3 = __expf(v3);
            }
            if (out_f32){
                float* o = (float*)D + (size_t)bz * sD;
                if (res){
                    const float* rp = res + (size_t)bz * sD;
                    v0 += rp[(size_t)r0 * ldD + col];
                    v1 += rp[(size_t)r0 * ldD + col + 1];
                    v2 += rp[(size_t)(r0 + 8) * ldD + col];
                    v3 += rp[(size_t)(r0 + 8) * ldD + col + 1];
                }
                *reinterpret_cast<float2*>(o + (size_t)r0 * ldD + col)       = make_float2(v0, v1);
                *reinterpret_cast<float2*>(o + (size_t)(r0 + 8) * ldD + col) = make_float2(v2, v3);
            } else {
                __half* o = (__half*)D + (size_t)bz * sD;
                *reinterpret_cast<uint32_t*>(o + (size_t)r0 * ldD + col)       = pack2(v0, v1);
                *reinterpret_cast<uint32_t*>(o + (size_t)(r0 + 8) * ldD + col) = pack2(v2, v3);
            }
        }
    }
}

// ============================ GroupNorm stats ============================
__global__ void __launch_bounds__(256) gn_stats(
    const float* __restrict__ x,
    const float* __restrict__ gamma,
    const float* __restrict__ beta)
{
    const int b = blockIdx.x >> 5;
    const int g = blockIdx.x & 31;
    const size_t base = ((size_t)b * CCH + (size_t)g * 16) * NSP;
    const float4* xp = reinterpret_cast<const float4*>(x + base);
    const int nv = 16 * NSP / 4;

    float s = 0.f, ss = 0.f;
    for (int i = threadIdx.x; i < nv; i += 256){
        float4 v = xp[i];
        s  += v.x + v.y + v.z + v.w;
        ss += v.x*v.x + v.y*v.y + v.z*v.z + v.w*v.w;
    }
    __shared__ float rs[256], rq[256];
    rs[threadIdx.x] = s; rq[threadIdx.x] = ss;
    __syncthreads();
    #pragma unroll
    for (int o = 128; o > 0; o >>= 1){
        if (threadIdx.x < o){ rs[threadIdx.x] += rs[threadIdx.x + o]; rq[threadIdx.x] += rq[threadIdx.x + o]; }
        __syncthreads();
    }
    if (threadIdx.x < 16){
        const float inv_n = 1.f / (float)(16 * NSP);
        const float mean = rs[0] * inv_n;
        const float var  = rq[0] * inv_n - mean * mean;
        const float inv  = rsqrtf(var + 1e-6f);
        const int c = g * 16 + threadIdx.x;
        const float ga = gamma[c] * inv;
        g_ga[b * CCH + c] = ga;
        g_be[b * CCH + c] = beta[c] - mean * ga;
    }
}

// ============================ normalize + transpose -> hnT fp16 ============================
__global__ void __launch_bounds__(256) norm_transpose(const float* __restrict__ x)
{
    __shared__ float t[64][65];
    const int b  = blockIdx.z;
    const int n0 = blockIdx.x * 64;
    const int c0 = blockIdx.y * 64;
    const int tid = threadIdx.x;
    const int r = tid >> 2, cs = (tid & 3) * 16;

    const float ga = g_ga[b * CCH + c0 + r];
    const float be = g_be[b * CCH + c0 + r];
    const float4* src = reinterpret_cast<const float4*>(
        x + (size_t)b * CCH * NSP + (size_t)(c0 + r) * NSP + n0 + cs);
    #pragma unroll
    for (int i = 0; i < 4; i++){
        float4 v = src[i];
        t[r][cs + 4*i + 0] = v.x * ga + be;
        t[r][cs + 4*i + 1] = v.y * ga + be;
        t[r][cs + 4*i + 2] = v.z * ga + be;
        t[r][cs + 4*i + 3] = v.w * ga + be;
    }
    __syncthreads();

    __half* dst = reinterpret_cast<__half*>(gh_hnT)
        + (size_t)b * NSP * CCH + (size_t)(n0 + r) * CCH + c0 + cs;
    uint32_t pk[8];
    #pragma unroll
    for (int j = 0; j < 8; j++)
        pk[j] = pack2(t[cs + 2*j][r], t[cs + 2*j + 1][r]);
    reinterpret_cast<uint4*>(dst)[0] = make_uint4(pk[0], pk[1], pk[2], pk[3]);
    reinterpret_cast<uint4*>(dst)[1] = make_uint4(pk[4], pk[5], pk[6], pk[7]);
}

// ============================ weights fp32 -> fp16 + bias pack ============================
__global__ void conv_w4(const float* __restrict__ w0, const float* __restrict__ w1,
                        const float* __restrict__ w2, const float* __restrict__ w3,
                        const float* __restrict__ bq, const float* __restrict__ bk,
                        unsigned short* __restrict__ dst)
{
    const int WN = CCH * CCH;
    int i = blockIdx.x * 256 + threadIdx.x;
    const float* srcs[4] = {w0, w1, w2, w3};
    if (i < 4 * WN){
        __half h = __float2half_rn(srcs[i >> 18][i & (WN - 1)]);
        dst[i] = *reinterpret_cast<unsigned short*>(&h);
    }
    if (i < CCH){ g_bqk[i] = bq[i]; g_bqk[CCH + i] = bk[i]; }
}

// ============================ row-sum reciprocal of exp-scores ============================
// One block (128 threads) per attention row: sum 4096 fp16, write 1/sum.
__global__ void __launch_bounds__(128) rowsum_inv()
{
    const uint4* p = reinterpret_cast<const uint4*>(gh_attn) + (size_t)blockIdx.x * (NSP / 8);
    const int tid = threadIdx.x;

    float sum = 0.f;
    #pragma unroll
    for (int i = 0; i < 4; i++){
        uint4 raw = p[tid + i * 128];
        const uint32_t* w = reinterpret_cast<const uint32_t*>(&raw);
        #pragma unroll
        for (int j = 0; j < 4; j++){
            float2 v = __half22float2(*reinterpret_cast<const __half2*>(&w[j]));
            sum += v.x + v.y;
        }
    }
    #pragma unroll
    for (int o = 16; o > 0; o >>= 1) sum += __shfl_xor_sync(0xffffffffu, sum, o);

    __shared__ float red[4];
    if ((tid & 31) == 0) red[tid >> 5] = sum;
    __syncthreads();
    if (tid == 0){
        float s = red[0] + red[1] + red[2] + red[3];
        g_rinv[blockIdx.x] = 1.f / s;
    }
}

// ============================ launch ============================
extern "C" void kernel_launch(void* const* d_in, const int* in_sizes, int n_in,
                              void* d_out, int out_size)
{
    const float* x     = (const float*)d_in[0];
    const float* gamma = (const float*)d_in[1];
    const float* beta  = (const float*)d_in[2];
    const float* wq    = (const float*)d_in[3];
    const float* bq    = (const float*)d_in[4];
    const float* wk    = (const float*)d_in[5];
    const float* bk    = (const float*)d_in[6];
    const float* wv    = (const float*)d_in[7];
    const float* bv    = (const float*)d_in[8];
    const float* wo    = (const float*)d_in[9];
    const float* bo    = (const float*)d_in[10];
    float* out = (float*)d_out;

    unsigned short *p_hnT, *p_qkT, *p_v, *p_oT, *p_w, *p_attnh;
    float *p_bqk, *p_rinv;
    cudaGetSymbolAddress((void**)&p_hnT,   gh_hnT);
    cudaGetSymbolAddress((void**)&p_qkT,   gh_qkT);
    cudaGetSymbolAddress((void**)&p_v,     gh_v);
    cudaGetSymbolAddress((void**)&p_oT,    gh_oT);
    cudaGetSymbolAddress((void**)&p_w,     gh_w);
    cudaGetSymbolAddress((void**)&p_attnh, gh_attn);
    cudaGetSymbolAddress((void**)&p_bqk,   g_bqk);
    cudaGetSymbolAddress((void**)&p_rinv,  g_rinv);

    cudaFuncSetAttribute(hgemm, cudaFuncAttributeMaxDynamicSharedMemorySize, SMEM_BYTES);

    const int WN = CCH * CCH;
    conv_w4<<<(4 * WN + 255)/256, 256>>>(wq, wk, wv, wo, bq, bk, p_w);

    gn_stats<<<BATCH * 32, 256>>>(x, gamma, beta);
    norm_transpose<<<dim3(NSP/64, CCH/64, BATCH), 256>>>(x);

    const size_t sNC = (size_t)NSP * CCH;
    const size_t sQK = (size_t)NSP * 2 * CCH;
    const size_t sAT = (size_t)NSP * NSP;
    const __half* hw   = (const __half*)p_w;
    const __half* hhnT = (const __half*)p_hnT;

    // fused q|k: qkT[n][co] = hnT . [Wq;Wk]^T + [bq;bk]   (M=4096, N=1024, K=512)
    const dim3 g_qk(2*CCH/128, NSP/128, BATCH);
    hgemm<<<g_qk, 256, SMEM_BYTES>>>(hhnT, hw, p_bqk, nullptr, nullptr, p_qkT,
                                     CCH, CCH, CCH, 2*CCH, sNC, 0, sQK, 1.f, 1, 0, 0);

    // v[co][n] = Wv . hnT^T + bv    (M=512, N=4096, K=512)
    const dim3 g_cn(NSP/128, CCH/128, BATCH);
    hgemm<<<g_cn, 256, SMEM_BYTES>>>(hw + 2*(size_t)WN, hhnT, bv, nullptr, nullptr, p_v,
                                     CCH, CCH, CCH, NSP, 0, sNC, sNC, 1.f, 0, 0, 0);

    // exp-scores[nq][nk] = exp(scale * q . k)   (M=N=4096, K=512), fp16 out
    const dim3 g_ss(NSP/128, NSP/128, BATCH);
    hgemm<<<g_ss, 256, SMEM_BYTES>>>((const __half*)p_qkT, (const __half*)p_qkT + CCH,
                                     nullptr, nullptr, nullptr, p_attnh,
                                     CCH, 2*CCH, 2*CCH, NSP, sQK, sQK, sAT,
                                     0.04419417382415922f, 0, 0, 1);

    rowsum_inv<<<BATCH * NSP, 128>>>();

    // oT[nq][c] = rinv[nq] * (expS . v^T)   (M=4096, N=512, K=4096)
    const dim3 g_nq(CCH/128, NSP/128, BATCH);
    hgemm<<<g_nq, 256, SMEM_BYTES>>>((const __half*)p_attnh, (const __half*)p_v,
                                     nullptr, nullptr, p_rinv, p_oT,
                                     NSP, NSP, NSP, CCH, sAT, sNC, sNC, 1.f, 0, 0, 0);

    // out[co][n] = Wo . oT^T + bo + x   (M=512, N=4096, K=512), fp32 out + residual
    hgemm<<<g_cn, 256, SMEM_BYTES>>>(hw + 3*(size_t)WN, (const __half*)p_oT, bo, x, nullptr, out,
                                     CCH, CCH, CCH, NSP, 0, sNC, (size_t)CCH * NSP, 1.f, 0, 1, 0);
}

// round 11
// speedup vs baseline: 1.0051x; 1.0051x over previous
#include <cuda_runtime.h>
#include <cuda_fp16.h>
#include <math.h>
#include <stdint.h>

#define BATCH 4
#define CCH   512
#define NSP   4096

// ---------------- scratch (static device globals; allocation-free) ----------------
__device__ unsigned short gh_hnT [(size_t)BATCH * NSP * CCH];        // [b][n][c] fp16
__device__ unsigned short gh_qkT [(size_t)BATCH * NSP * 2 * CCH];    // [b][n][0:512 q | 512:1024 k]
__device__ unsigned short gh_v   [(size_t)BATCH * CCH * NSP];        // [b][c][n]
__device__ unsigned short gh_oT  [(size_t)BATCH * NSP * CCH];        // [b][n][c]
__device__ unsigned short gh_w   [(size_t)4 * CCH * CCH];            // wq,wk,wv,wo fp16
__device__ unsigned short gh_attn[(size_t)BATCH * NSP * NSP];        // fp16 exp-scores
__device__ float g_ga[BATCH * CCH];
__device__ float g_be[BATCH * CCH];
__device__ float g_bqk[2 * CCH];
__device__ float g_rsum[(size_t)BATCH * NSP];                        // row sums (atomic)

// ---------------- helpers ----------------
__device__ __forceinline__ void cpa16(void* dst, const void* src){
    uint32_t s = (uint32_t)__cvta_generic_to_shared(dst);
    asm volatile("cp.async.cg.shared.global [%0], [%1], 16;" :: "r"(s), "l"(src));
}
#define CP_COMMIT() asm volatile("cp.async.commit_group;")

__device__ __forceinline__ void ldm_x4(uint32_t* r, const void* p){
    uint32_t a = (uint32_t)__cvta_generic_to_shared(p);
    asm volatile("ldmatrix.sync.aligned.m8n8.x4.shared.b16 {%0,%1,%2,%3}, [%4];"
        : "=r"(r[0]), "=r"(r[1]), "=r"(r[2]), "=r"(r[3]) : "r"(a));
}

__device__ __forceinline__ void mma16(float* c, const uint32_t* a, const uint32_t* b){
    asm volatile(
      "mma.sync.aligned.m16n8k16.row.col.f32.f16.f16.f32 "
      "{%0,%1,%2,%3},{%4,%5,%6,%7},{%8,%9},{%0,%1,%2,%3};"
      : "+f"(c[0]), "+f"(c[1]), "+f"(c[2]), "+f"(c[3])
      : "r"(a[0]), "r"(a[1]), "r"(a[2]), "r"(a[3]), "r"(b[0]), "r"(b[1]));
}

__device__ __forceinline__ uint32_t pack2(float x, float y){
    __half2 h = __floats2half2_rn(x, y);
    return *reinterpret_cast<uint32_t*>(&h);
}

// XOR-swizzled offset within a 128-row x 64-half tile (row stride 128 B).
__device__ __forceinline__ int swz(int r, int c){
    return r * 64 + ((((c >> 3) ^ (r & 7)) & 7) << 3) + (c & 7);
}

// ============================ fp16 tensor-core GEMM ============================
// BM=128, BN=128, BK=64, 256 threads, warp grid 2(M) x 4(N), warp tile 64x32.
// 3-stage cp.async pipeline (issue-early, wait_group 2), XOR swizzle.
// D[m][n] = scale * sum_k A[m][k] * B[n][k]  (+bias)
// rowptr semantics: do_exp=1 -> atomicAdd per-row sums of exp values into rowptr;
//                   do_exp=0 & rowptr -> multiply row by 1/rowptr[row].
#define TILE_H (128 * 64)
#define BUF_H  (2 * TILE_H)
#define SMEM_BYTES (3 * BUF_H * 2)        // 98304 B

__global__ void __launch_bounds__(256, 2) hgemm(
    const __half* __restrict__ A, const __half* __restrict__ B,
    const float* __restrict__ bias, const float* __restrict__ res,
    float* __restrict__ rowptr,
    void* __restrict__ D,
    int K, int ldA, int ldB, int ldD,
    size_t sA, size_t sB, size_t sD,
    float scale, int bias_col, int out_f32, int do_exp)
{
    extern __shared__ __half smh[];

    const int tid = threadIdx.x, lane = tid & 31, wid = tid >> 5;
    const int g = lane >> 2, tig = lane & 3;
    const int wm = wid >> 2, wn = wid & 3;
    const int m0 = blockIdx.y * 128, n0 = blockIdx.x * 128;
    const int bz = blockIdx.z;

    const __half* Ag = A + (size_t)bz * sA;
    const __half* Bg = B + (size_t)bz * sB;
    float* rp_row = rowptr ? rowptr + (size_t)bz * (gridDim.y * 128) : nullptr;

    float acc[4][4][4];
    #pragma unroll
    for (int i = 0; i < 4; i++)
        #pragma unroll
        for (int j = 0; j < 4; j++)
            #pragma unroll
            for (int r = 0; r < 4; r++) acc[i][j][r] = 0.f;

    const int NK = K >> 6;

    auto stage = [&](int ks){
        __half* Asm = smh + (ks % 3) * BUF_H;
        __half* Bsm = Asm + TILE_H;
        #pragma unroll
        for (int it = 0; it < 4; it++){
            const int idx = it * 256 + tid;
            const int r = idx >> 3, c = (idx & 7) * 8;
            const int so = swz(r, c);
            cpa16(Asm + so, Ag + (size_t)(m0 + r) * ldA + ks * 64 + c);
            cpa16(Bsm + so, Bg + (size_t)(n0 + r) * ldB + ks * 64 + c);
        }
        CP_COMMIT();
    };

    stage(0);
    if (NK > 1) stage(1);

    const int a_row  = (lane & 15);
    const int a_koff = (lane >> 4) * 8;
    const int b_row  = ((lane >> 4) << 3) + (lane & 7);
    const int b_koff = ((lane >> 3) & 1) * 8;

    for (int ks = 0; ks < NK; ks++){
        if (ks + 2 < NK) { stage(ks + 2); asm volatile("cp.async.wait_group 2;"); }
        else if (ks + 1 < NK) { asm volatile("cp.async.wait_group 1;"); }
        else { asm volatile("cp.async.wait_group 0;"); }
        __syncthreads();

        const __half* Asm = smh + (ks % 3) * BUF_H;
        const __half* Bsm = Asm + TILE_H;

        #pragma unroll
        for (int kk = 0; kk < 64; kk += 16){
            uint32_t a[4][4], b[4][2];
            #pragma unroll
            for (int mi = 0; mi < 4; mi++)
                ldm_x4(a[mi], Asm + swz(wm*64 + mi*16 + a_row, kk + a_koff));
            #pragma unroll
            for (int pj = 0; pj < 2; pj++){
                uint32_t t4[4];
                ldm_x4(t4, Bsm + swz(wn*32 + pj*16 + b_row, kk + b_koff));
                b[2*pj  ][0] = t4[0]; b[2*pj  ][1] = t4[1];
                b[2*pj+1][0] = t4[2]; b[2*pj+1][1] = t4[3];
            }
            #pragma unroll
            for (int mi = 0; mi < 4; mi++)
                #pragma unroll
                for (int nj = 0; nj < 4; nj++)
                    mma16(acc[mi][nj], a[mi], b[nj]);
        }
        __syncthreads();
    }

    // ---------------- epilogue ----------------
    #pragma unroll
    for (int mi = 0; mi < 4; mi++){
        const int r0 = m0 + wm * 64 + mi * 16 + g;
        float br0 = 0.f, br1 = 0.f;
        if (bias && !bias_col){ br0 = bias[r0]; br1 = bias[r0 + 8]; }
        float rs0 = 1.f, rs1 = 1.f;
        if (rp_row && !do_exp){ rs0 = 1.f / rp_row[r0]; rs1 = 1.f / rp_row[r0 + 8]; }
        float sum0 = 0.f, sum1 = 0.f;
        #pragma unroll
        for (int nj = 0; nj < 4; nj++){
            const int col = n0 + wn * 32 + nj * 8 + tig * 2;
            float v0 = acc[mi][nj][0] * scale;
            float v1 = acc[mi][nj][1] * scale;
            float v2 = acc[mi][nj][2] * scale;
            float v3 = acc[mi][nj][3] * scale;
            if (bias){
                if (bias_col){
                    const float bc0 = bias[col], bc1 = bias[col + 1];
                    v0 += bc0; v1 += bc1; v2 += bc0; v3 += bc1;
                } else {
                    v0 += br0; v1 += br0; v2 += br1; v3 += br1;
                }
            }
            if (!do_exp && rp_row){ v0 *= rs0; v1 *= rs0; v2 *= rs1; v3 *= rs1; }
            if (do_exp){
                v0 = __expf(v0); v1 = __expf(v1);
                v2 = __expf(v2); v3 = __expf(v3);
                sum0 += v0 + v1; sum1 += v2 + v3;
            }
            if (out_f32){
                float* o = (float*)D + (size_t)bz * sD;
                if (res){
                    const float* rp = res + (size_t)bz * sD;
                    v0 += rp[(size_t)r0 * ldD + col];
                    v1 += rp[(size_t)r0 * ldD + col + 1];
                    v2 += rp[(size_t)(r0 + 8) * ldD + col];
                    v3 += rp[(size_t)(r0 + 8) * ldD + col + 1];
                }
                *reinterpret_cast<float2*>(o + (size_t)r0 * ldD + col)       = make_float2(v0, v1);
                *reinterpret_cast<float2*>(o + (size_t)(r0 + 8) * ldD + col) = make_float2(v2, v3);
            } else {
                __half* o = (__half*)D + (size_t)bz * sD;
                *reinterpret_cast<uint32_t*>(o + (size_t)r0 * ldD + col)       = pack2(v0, v1);
                *reinterpret_cast<uint32_t*>(o + (size_t)(r0 + 8) * ldD + col) = pack2(v2, v3);
            }
        }
        if (do_exp && rp_row){
            // reduce across the quad (4 lanes share each row pair), then one atomic per row
            sum0 += __shfl_xor_sync(0xffffffffu, sum0, 1);
            sum0 += __shfl_xor_sync(0xffffffffu, sum0, 2);
            sum1 += __shfl_xor_sync(0xffffffffu, sum1, 1);
            sum1 += __shfl_xor_sync(0xffffffffu, sum1, 2);
            if (tig == 0){
                atomicAdd(&rp_row[r0], sum0);
                atomicAdd(&rp_row[r0 + 8], sum1);
            }
        }
    }
}

// ============================ GroupNorm stats ============================
__global__ void __launch_bounds__(256) gn_stats(
    const float* __restrict__ x,
    const float* __restrict__ gamma,
    const float* __restrict__ beta)
{
    const int b = blockIdx.x >> 5;
    const int g = blockIdx.x & 31;
    const size_t base = ((size_t)b * CCH + (size_t)g * 16) * NSP;
    const float4* xp = reinterpret_cast<const float4*>(x + base);
    const int nv = 16 * NSP / 4;

    float s = 0.f, ss = 0.f;
    for (int i = threadIdx.x; i < nv; i += 256){
        float4 v = xp[i];
        s  += v.x + v.y + v.z + v.w;
        ss += v.x*v.x + v.y*v.y + v.z*v.z + v.w*v.w;
    }
    __shared__ float rs[256], rq[256];
    rs[threadIdx.x] = s; rq[threadIdx.x] = ss;
    __syncthreads();
    #pragma unroll
    for (int o = 128; o > 0; o >>= 1){
        if (threadIdx.x < o){ rs[threadIdx.x] += rs[threadIdx.x + o]; rq[threadIdx.x] += rq[threadIdx.x + o]; }
        __syncthreads();
    }
    if (threadIdx.x < 16){
        const float inv_n = 1.f / (float)(16 * NSP);
        const float mean = rs[0] * inv_n;
        const float var  = rq[0] * inv_n - mean * mean;
        const float inv  = rsqrtf(var + 1e-6f);
        const int c = g * 16 + threadIdx.x;
        const float ga = gamma[c] * inv;
        g_ga[b * CCH + c] = ga;
        g_be[b * CCH + c] = beta[c] - mean * ga;
    }
}

// ============================ normalize + transpose -> hnT fp16 ============================
__global__ void __launch_bounds__(256) norm_transpose(const float* __restrict__ x)
{
    __shared__ float t[64][65];
    const int b  = blockIdx.z;
    const int n0 = blockIdx.x * 64;
    const int c0 = blockIdx.y * 64;
    const int tid = threadIdx.x;
    const int r = tid >> 2, cs = (tid & 3) * 16;

    const float ga = g_ga[b * CCH + c0 + r];
    const float be = g_be[b * CCH + c0 + r];
    const float4* src = reinterpret_cast<const float4*>(
        x + (size_t)b * CCH * NSP + (size_t)(c0 + r) * NSP + n0 + cs);
    #pragma unroll
    for (int i = 0; i < 4; i++){
        float4 v = src[i];
        t[r][cs + 4*i + 0] = v.x * ga + be;
        t[r][cs + 4*i + 1] = v.y * ga + be;
        t[r][cs + 4*i + 2] = v.z * ga + be;
        t[r][cs + 4*i + 3] = v.w * ga + be;
    }
    __syncthreads();

    __half* dst = reinterpret_cast<__half*>(gh_hnT)
        + (size_t)b * NSP * CCH + (size_t)(n0 + r) * CCH + c0 + cs;
    uint32_t pk[8];
    #pragma unroll
    for (int j = 0; j < 8; j++)
        pk[j] = pack2(t[cs + 2*j][r], t[cs + 2*j + 1][r]);
    reinterpret_cast<uint4*>(dst)[0] = make_uint4(pk[0], pk[1], pk[2], pk[3]);
    reinterpret_cast<uint4*>(dst)[1] = make_uint4(pk[4], pk[5], pk[6], pk[7]);
}

// ============================ weights fp32 -> fp16 + bias pack + rsum zero ============================
__global__ void conv_w4(const float* __restrict__ w0, const float* __restrict__ w1,
                        const float* __restrict__ w2, const float* __restrict__ w3,
                        const float* __restrict__ bq, const float* __restrict__ bk,
                        unsigned short* __restrict__ dst)
{
    const int WN = CCH * CCH;
    int i = blockIdx.x * 256 + threadIdx.x;
    const float* srcs[4] = {w0, w1, w2, w3};
    if (i < 4 * WN){
        __half h = __float2half_rn(srcs[i >> 18][i & (WN - 1)]);
        dst[i] = *reinterpret_cast<unsigned short*>(&h);
    }
    if (i < CCH){ g_bqk[i] = bq[i]; g_bqk[CCH + i] = bk[i]; }
    if (i < BATCH * NSP) g_rsum[i] = 0.f;
}

// ============================ launch ============================
extern "C" void kernel_launch(void* const* d_in, const int* in_sizes, int n_in,
                              void* d_out, int out_size)
{
    const float* x     = (const float*)d_in[0];
    const float* gamma = (const float*)d_in[1];
    const float* beta  = (const float*)d_in[2];
    const float* wq    = (const float*)d_in[3];
    const float* bq    = (const float*)d_in[4];
    const float* wk    = (const float*)d_in[5];
    const float* bk    = (const float*)d_in[6];
    const float* wv    = (const float*)d_in[7];
    const float* bv    = (const float*)d_in[8];
    const float* wo    = (const float*)d_in[9];
    const float* bo    = (const float*)d_in[10];
    float* out = (float*)d_out;

    unsigned short *p_hnT, *p_qkT, *p_v, *p_oT, *p_w, *p_attnh;
    float *p_bqk, *p_rsum;
    cudaGetSymbolAddress((void**)&p_hnT,   gh_hnT);
    cudaGetSymbolAddress((void**)&p_qkT,   gh_qkT);
    cudaGetSymbolAddress((void**)&p_v,     gh_v);
    cudaGetSymbolAddress((void**)&p_oT,    gh_oT);
    cudaGetSymbolAddress((void**)&p_w,     gh_w);
    cudaGetSymbolAddress((void**)&p_attnh, gh_attn);
    cudaGetSymbolAddress((void**)&p_bqk,   g_bqk);
    cudaGetSymbolAddress((void**)&p_rsum,  g_rsum);

    cudaFuncSetAttribute(hgemm, cudaFuncAttributeMaxDynamicSharedMemorySize, SMEM_BYTES);

    const int WN = CCH * CCH;
    conv_w4<<<(4 * WN + 255)/256, 256>>>(wq, wk, wv, wo, bq, bk, p_w);

    gn_stats<<<BATCH * 32, 256>>>(x, gamma, beta);
    norm_transpose<<<dim3(NSP/64, CCH/64, BATCH), 256>>>(x);

    const size_t sNC = (size_t)NSP * CCH;
    const size_t sQK = (size_t)NSP * 2 * CCH;
    const size_t sAT = (size_t)NSP * NSP;
    const __half* hw   = (const __half*)p_w;
    const __half* hhnT = (const __half*)p_hnT;

    // fused q|k: qkT[n][co] = hnT . [Wq;Wk]^T + [bq;bk]   (M=4096, N=1024, K=512)
    const dim3 g_qk(2*CCH/128, NSP/128, BATCH);
    hgemm<<<g_qk, 256, SMEM_BYTES>>>(hhnT, hw, p_bqk, nullptr, nullptr, p_qkT,
                                     CCH, CCH, CCH, 2*CCH, sNC, 0, sQK, 1.f, 1, 0, 0);

    // v[co][n] = Wv . hnT^T + bv    (M=512, N=4096, K=512)
    const dim3 g_cn(NSP/128, CCH/128, BATCH);
    hgemm<<<g_cn, 256, SMEM_BYTES>>>(hw + 2*(size_t)WN, hhnT, bv, nullptr, nullptr, p_v,
                                     CCH, CCH, CCH, NSP, 0, sNC, sNC, 1.f, 0, 0, 0);

    // exp-scores[nq][nk] = exp(scale * q . k), fp16 out; row sums accumulated atomically
    const dim3 g_ss(NSP/128, NSP/128, BATCH);
    hgemm<<<g_ss, 256, SMEM_BYTES>>>((const __half*)p_qkT, (const __half*)p_qkT + CCH,
                                     nullptr, nullptr, p_rsum, p_attnh,
                                     CCH, 2*CCH, 2*CCH, NSP, sQK, sQK, sAT,
                                     0.04419417382415922f, 0, 0, 1);

    // oT[nq][c] = (1/rsum[nq]) * (expS . v^T)   (M=4096, N=512, K=4096)
    const dim3 g_nq(CCH/128, NSP/128, BATCH);
    hgemm<<<g_nq, 256, SMEM_BYTES>>>((const __half*)p_attnh, (const __half*)p_v,
                                     nullptr, nullptr, p_rsum, p_oT,
                                     NSP, NSP, NSP, CCH, sAT, sNC, sNC, 1.f, 0, 0, 0);

    // out[co][n] = Wo . oT^T + bo + x   (M=512, N=4096, K=512), fp32 out + residual
    hgemm<<<g_cn, 256, SMEM_BYTES>>>(hw + 3*(size_t)WN, (const __half*)p_oT, bo, x, nullptr, out,
                                     CCH, CCH, CCH, NSP, 0, sNC, (size_t)CCH * NSP, 1.f, 0, 1, 0);
}

// round 12
// speedup vs baseline: 1.0482x; 1.0429x over previous
#include <cuda_runtime.h>
#include <cuda_fp16.h>
#include <math.h>
#include <stdint.h>

#define BATCH 4
#define CCH   512
#define NSP   4096

// ---------------- scratch (static device globals; allocation-free) ----------------
__device__ unsigned short gh_hnT [(size_t)BATCH * NSP * CCH];        // [b][n][c] fp16
__device__ unsigned short gh_qkT [(size_t)BATCH * NSP * 2 * CCH];    // [b][n][0:512 q | 512:1024 k]
__device__ unsigned short gh_v   [(size_t)BATCH * CCH * NSP];        // [b][c][n]
__device__ unsigned short gh_oT  [(size_t)BATCH * NSP * CCH];        // [b][n][c]
__device__ unsigned short gh_w   [(size_t)4 * CCH * CCH];            // wq,wk,wv,wo fp16
__device__ unsigned short gh_attn[(size_t)BATCH * NSP * NSP];        // fp16 exp-scores
__device__ float g_ga[BATCH * CCH];
__device__ float g_be[BATCH * CCH];
__device__ float g_bqk[2 * CCH];
__device__ float g_rsum[(size_t)BATCH * NSP];                        // row sums (atomic)

// ---------------- helpers ----------------
__device__ __forceinline__ void cpa16(void* dst, const void* src){
    uint32_t s = (uint32_t)__cvta_generic_to_shared(dst);
    asm volatile("cp.async.cg.shared.global [%0], [%1], 16;" :: "r"(s), "l"(src));
}
#define CP_COMMIT() asm volatile("cp.async.commit_group;")

__device__ __forceinline__ void ldm_x4u(uint32_t* r, uint32_t a){
    asm volatile("ldmatrix.sync.aligned.m8n8.x4.shared.b16 {%0,%1,%2,%3}, [%4];"
        : "=r"(r[0]), "=r"(r[1]), "=r"(r[2]), "=r"(r[3]) : "r"(a));
}

__device__ __forceinline__ void mma16(float* c, const uint32_t* a, const uint32_t* b){
    asm volatile(
      "mma.sync.aligned.m16n8k16.row.col.f32.f16.f16.f32 "
      "{%0,%1,%2,%3},{%4,%5,%6,%7},{%8,%9},{%0,%1,%2,%3};"
      : "+f"(c[0]), "+f"(c[1]), "+f"(c[2]), "+f"(c[3])
      : "r"(a[0]), "r"(a[1]), "r"(a[2]), "r"(a[3]), "r"(b[0]), "r"(b[1]));
}

__device__ __forceinline__ uint32_t pack2(float x, float y){
    __half2 h = __floats2half2_rn(x, y);
    return *reinterpret_cast<uint32_t*>(&h);
}

// XOR-swizzled offset (in halfs) within a 128-row x 64-half tile (row stride 128 B).
__device__ __forceinline__ int swz(int r, int c){
    return r * 64 + ((((c >> 3) ^ (r & 7)) & 7) << 3) + (c & 7);
}

// ============================ fp16 tensor-core GEMM ============================
// BM=128, BN=128, BK=64, 256 threads, warp grid 2(M) x 4(N), warp tile 64x32.
// 3-stage cp.async pipeline, XOR swizzle, single __syncthreads per iteration
// (barrier at top proves compute(ks-1) done => buffer (ks+2)%3 is free).
// Fragment addresses: addr(kk) = base ^ (kk*2 bytes)  [kk toggles only swizzle bits].
#define TILE_H (128 * 64)
#define BUF_H  (2 * TILE_H)
#define SMEM_BYTES (3 * BUF_H * 2)        // 98304 B

__global__ void __launch_bounds__(256, 2) hgemm(
    const __half* __restrict__ A, const __half* __restrict__ B,
    const float* __restrict__ bias, const float* __restrict__ res,
    float* __restrict__ rowptr,
    void* __restrict__ D,
    int K, int ldA, int ldB, int ldD,
    size_t sA, size_t sB, size_t sD,
    float scale, int bias_col, int out_f32, int do_exp)
{
    extern __shared__ __half smh[];

    const int tid = threadIdx.x, lane = tid & 31, wid = tid >> 5;
    const int g = lane >> 2, tig = lane & 3;
    const int wm = wid >> 2, wn = wid & 3;
    const int m0 = blockIdx.y * 128, n0 = blockIdx.x * 128;
    const int bz = blockIdx.z;

    const __half* Ag = A + (size_t)bz * sA;
    const __half* Bg = B + (size_t)bz * sB;
    float* rp_row = rowptr ? rowptr + (size_t)bz * (gridDim.y * 128) : nullptr;

    float acc[4][4][4];
    #pragma unroll
    for (int i = 0; i < 4; i++)
        #pragma unroll
        for (int j = 0; j < 4; j++)
            #pragma unroll
            for (int r = 0; r < 4; r++) acc[i][j][r] = 0.f;

    const int NK = K >> 6;

    auto stage = [&](int ks){
        __half* Asm = smh + (ks % 3) * BUF_H;
        __half* Bsm = Asm + TILE_H;
        #pragma unroll
        for (int it = 0; it < 4; it++){
            const int idx = it * 256 + tid;
            const int r = idx >> 3, c = (idx & 7) * 8;
            const int so = swz(r, c);
            cpa16(Asm + so, Ag + (size_t)(m0 + r) * ldA + ks * 64 + c);
            cpa16(Bsm + so, Bg + (size_t)(n0 + r) * ldB + ks * 64 + c);
        }
        CP_COMMIT();
    };

    stage(0);
    if (NK > 1) stage(1);

    // ---- precomputed fragment base byte-offsets (kk=0); addr(kk) = base ^ (kk*2) ----
    const uint32_t sbase = (uint32_t)__cvta_generic_to_shared(smh);
    const int a_row  = (lane & 15);
    const int a_koff = (lane >> 4) * 8;
    const int b_row  = ((lane >> 4) << 3) + (lane & 7);
    const int b_koff = ((lane >> 3) & 1) * 8;

    uint32_t aoff[4], boff[2];
    #pragma unroll
    for (int mi = 0; mi < 4; mi++)
        aoff[mi] = (uint32_t)(swz(wm*64 + mi*16 + a_row, a_koff) * 2);
    #pragma unroll
    for (int pj = 0; pj < 2; pj++)
        boff[pj] = (uint32_t)((TILE_H + swz(wn*32 + pj*16 + b_row, b_koff)) * 2);

    for (int ks = 0; ks < NK; ks++){
        if (ks + 1 < NK) { asm volatile("cp.async.wait_group 1;"); }
        else             { asm volatile("cp.async.wait_group 0;"); }
        __syncthreads();
        if (ks + 2 < NK) stage(ks + 2);

        const uint32_t bufb = sbase + (uint32_t)((ks % 3) * (BUF_H * 2));

        #pragma unroll
        for (int kk = 0; kk < 4; kk++){
            const uint32_t kx = (uint32_t)(kk * 32);   // kk*16 halfs * 2 bytes
            uint32_t a[4][4], b[4][2];
            #pragma unroll
            for (int mi = 0; mi < 4; mi++)
                ldm_x4u(a[mi], bufb + (aoff[mi] ^ kx));
            #pragma unroll
            for (int pj = 0; pj < 2; pj++){
                uint32_t t4[4];
                ldm_x4u(t4, bufb + (boff[pj] ^ kx));
                b[2*pj  ][0] = t4[0]; b[2*pj  ][1] = t4[1];
                b[2*pj+1][0] = t4[2]; b[2*pj+1][1] = t4[3];
            }
            #pragma unroll
            for (int mi = 0; mi < 4; mi++)
                #pragma unroll
                for (int nj = 0; nj < 4; nj++)
                    mma16(acc[mi][nj], a[mi], b[nj]);
        }
    }

    __syncthreads();   // protect smem before any (none) reuse; cheap, keeps epilogue ordered after last reads

    // ---------------- epilogue ----------------
    #pragma unroll
    for (int mi = 0; mi < 4; mi++){
        const int r0 = m0 + wm * 64 + mi * 16 + g;
        float br0 = 0.f, br1 = 0.f;
        if (bias && !bias_col){ br0 = bias[r0]; br1 = bias[r0 + 8]; }
        float rs0 = 1.f, rs1 = 1.f;
        if (rp_row && !do_exp){ rs0 = 1.f / rp_row[r0]; rs1 = 1.f / rp_row[r0 + 8]; }
        float sum0 = 0.f, sum1 = 0.f;
        #pragma unroll
        for (int nj = 0; nj < 4; nj++){
            const int col = n0 + wn * 32 + nj * 8 + tig * 2;
            float v0 = acc[mi][nj][0] * scale;
            float v1 = acc[mi][nj][1] * scale;
            float v2 = acc[mi][nj][2] * scale;
            float v3 = acc[mi][nj][3] * scale;
            if (bias){
                if (bias_col){
                    const float bc0 = bias[col], bc1 = bias[col + 1];
                    v0 += bc0; v1 += bc1; v2 += bc0; v3 += bc1;
                } else {
                    v0 += br0; v1 += br0; v2 += br1; v3 += br1;
                }
            }
            if (!do_exp && rp_row){ v0 *= rs0; v1 *= rs0; v2 *= rs1; v3 *= rs1; }
            if (do_exp){
                v0 = __expf(v0); v1 = __expf(v1);
                v2 = __expf(v2); v3 = __expf(v3);
                sum0 += v0 + v1; sum1 += v2 + v3;
            }
            if (out_f32){
                float* o = (float*)D + (size_t)bz * sD;
                if (res){
                    const float* rp = res + (size_t)bz * sD;
                    v0 += rp[(size_t)r0 * ldD + col];
                    v1 += rp[(size_t)r0 * ldD + col + 1];
                    v2 += rp[(size_t)(r0 + 8) * ldD + col];
                    v3 += rp[(size_t)(r0 + 8) * ldD + col + 1];
                }
                *reinterpret_cast<float2*>(o + (size_t)r0 * ldD + col)       = make_float2(v0, v1);
                *reinterpret_cast<float2*>(o + (size_t)(r0 + 8) * ldD + col) = make_float2(v2, v3);
            } else {
                __half* o = (__half*)D + (size_t)bz * sD;
                *reinterpret_cast<uint32_t*>(o + (size_t)r0 * ldD + col)       = pack2(v0, v1);
                *reinterpret_cast<uint32_t*>(o + (size_t)(r0 + 8) * ldD + col) = pack2(v2, v3);
            }
        }
        if (do_exp && rp_row){
            sum0 += __shfl_xor_sync(0xffffffffu, sum0, 1);
            sum0 += __shfl_xor_sync(0xffffffffu, sum0, 2);
            sum1 += __shfl_xor_sync(0xffffffffu, sum1, 1);
            sum1 += __shfl_xor_sync(0xffffffffu, sum1, 2);
            if (tig == 0){
                atomicAdd(&rp_row[r0], sum0);
                atomicAdd(&rp_row[r0 + 8], sum1);
            }
        }
    }
}

// ============================ GroupNorm stats ============================
__global__ void __launch_bounds__(256) gn_stats(
    const float* __restrict__ x,
    const float* __restrict__ gamma,
    const float* __restrict__ beta)
{
    const int b = blockIdx.x >> 5;
    const int g = blockIdx.x & 31;
    const size_t base = ((size_t)b * CCH + (size_t)g * 16) * NSP;
    const float4* xp = reinterpret_cast<const float4*>(x + base);
    const int nv = 16 * NSP / 4;

    float s = 0.f, ss = 0.f;
    for (int i = threadIdx.x; i < nv; i += 256){
        float4 v = xp[i];
        s  += v.x + v.y + v.z + v.w;
        ss += v.x*v.x + v.y*v.y + v.z*v.z + v.w*v.w;
    }
    __shared__ float rs[256], rq[256];
    rs[threadIdx.x] = s; rq[threadIdx.x] = ss;
    __syncthreads();
    #pragma unroll
    for (int o = 128; o > 0; o >>= 1){
        if (threadIdx.x < o){ rs[threadIdx.x] += rs[threadIdx.x + o]; rq[threadIdx.x] += rq[threadIdx.x + o]; }
        __syncthreads();
    }
    if (threadIdx.x < 16){
        const float inv_n = 1.f / (float)(16 * NSP);
        const float mean = rs[0] * inv_n;
        const float var  = rq[0] * inv_n - mean * mean;
        const float inv  = rsqrtf(var + 1e-6f);
        const int c = g * 16 + threadIdx.x;
        const float ga = gamma[c] * inv;
        g_ga[b * CCH + c] = ga;
        g_be[b * CCH + c] = beta[c] - mean * ga;
    }
}

// ============================ normalize + transpose -> hnT fp16 ============================
__global__ void __launch_bounds__(256) norm_transpose(const float* __restrict__ x)
{
    __shared__ float t[64][65];
    const int b  = blockIdx.z;
    const int n0 = blockIdx.x * 64;
    const int c0 = blockIdx.y * 64;
    const int tid = threadIdx.x;
    const int r = tid >> 2, cs = (tid & 3) * 16;

    const float ga = g_ga[b * CCH + c0 + r];
    const float be = g_be[b * CCH + c0 + r];
    const float4* src = reinterpret_cast<const float4*>(
        x + (size_t)b * CCH * NSP + (size_t)(c0 + r) * NSP + n0 + cs);
    #pragma unroll
    for (int i = 0; i < 4; i++){
        float4 v = src[i];
        t[r][cs + 4*i + 0] = v.x * ga + be;
        t[r][cs + 4*i + 1] = v.y * ga + be;
        t[r][cs + 4*i + 2] = v.z * ga + be;
        t[r][cs + 4*i + 3] = v.w * ga + be;
    }
    __syncthreads();

    __half* dst = reinterpret_cast<__half*>(gh_hnT)
        + (size_t)b * NSP * CCH + (size_t)(n0 + r) * CCH + c0 + cs;
    uint32_t pk[8];
    #pragma unroll
    for (int j = 0; j < 8; j++)
        pk[j] = pack2(t[cs + 2*j][r], t[cs + 2*j + 1][r]);
    reinterpret_cast<uint4*>(dst)[0] = make_uint4(pk[0], pk[1], pk[2], pk[3]);
    reinterpret_cast<uint4*>(dst)[1] = make_uint4(pk[4], pk[5], pk[6], pk[7]);
}

// ============================ weights fp32 -> fp16 + bias pack + rsum zero ============================
__global__ void conv_w4(const float* __restrict__ w0, const float* __restrict__ w1,
                        const float* __restrict__ w2, const float* __restrict__ w3,
                        const float* __restrict__ bq, const float* __restrict__ bk,
                        unsigned short* __restrict__ dst)
{
    const int WN = CCH * CCH;
    int i = blockIdx.x * 256 + threadIdx.x;
    const float* srcs[4] = {w0, w1, w2, w3};
    if (i < 4 * WN){
        __half h = __float2half_rn(srcs[i >> 18][i & (WN - 1)]);
        dst[i] = *reinterpret_cast<unsigned short*>(&h);
    }
    if (i < CCH){ g_bqk[i] = bq[i]; g_bqk[CCH + i] = bk[i]; }
    if (i < BATCH * NSP) g_rsum[i] = 0.f;
}

// ============================ launch ============================
extern "C" void kernel_launch(void* const* d_in, const int* in_sizes, int n_in,
                              void* d_out, int out_size)
{
    const float* x     = (const float*)d_in[0];
    const float* gamma = (const float*)d_in[1];
    const float* beta  = (const float*)d_in[2];
    const float* wq    = (const float*)d_in[3];
    const float* bq    = (const float*)d_in[4];
    const float* wk    = (const float*)d_in[5];
    const float* bk    = (const float*)d_in[6];
    const float* wv    = (const float*)d_in[7];
    const float* bv    = (const float*)d_in[8];
    const float* wo    = (const float*)d_in[9];
    const float* bo    = (const float*)d_in[10];
    float* out = (float*)d_out;

    unsigned short *p_hnT, *p_qkT, *p_v, *p_oT, *p_w, *p_attnh;
    float *p_bqk, *p_rsum;
    cudaGetSymbolAddress((void**)&p_hnT,   gh_hnT);
    cudaGetSymbolAddress((void**)&p_qkT,   gh_qkT);
    cudaGetSymbolAddress((void**)&p_v,     gh_v);
    cudaGetSymbolAddress((void**)&p_oT,    gh_oT);
    cudaGetSymbolAddress((void**)&p_w,     gh_w);
    cudaGetSymbolAddress((void**)&p_attnh, gh_attn);
    cudaGetSymbolAddress((void**)&p_bqk,   g_bqk);
    cudaGetSymbolAddress((void**)&p_rsum,  g_rsum);

    cudaFuncSetAttribute(hgemm, cudaFuncAttributeMaxDynamicSharedMemorySize, SMEM_BYTES);

    const int WN = CCH * CCH;
    conv_w4<<<(4 * WN + 255)/256, 256>>>(wq, wk, wv, wo, bq, bk, p_w);

    gn_stats<<<BATCH * 32, 256>>>(x, gamma, beta);
    norm_transpose<<<dim3(NSP/64, CCH/64, BATCH), 256>>>(x);

    const size_t sNC = (size_t)NSP * CCH;
    const size_t sQK = (size_t)NSP * 2 * CCH;
    const size_t sAT = (size_t)NSP * NSP;
    const __half* hw   = (const __half*)p_w;
    const __half* hhnT = (const __half*)p_hnT;

    // fused q|k: qkT[n][co] = hnT . [Wq;Wk]^T + [bq;bk]   (M=4096, N=1024, K=512)
    const dim3 g_qk(2*CCH/128, NSP/128, BATCH);
    hgemm<<<g_qk, 256, SMEM_BYTES>>>(hhnT, hw, p_bqk, nullptr, nullptr, p_qkT,
                                     CCH, CCH, CCH, 2*CCH, sNC, 0, sQK, 1.f, 1, 0, 0);

    // v[co][n] = Wv . hnT^T + bv    (M=512, N=4096, K=512)
    const dim3 g_cn(NSP/128, CCH/128, BATCH);
    hgemm<<<g_cn, 256, SMEM_BYTES>>>(hw + 2*(size_t)WN, hhnT, bv, nullptr, nullptr, p_v,
                                     CCH, CCH, CCH, NSP, 0, sNC, sNC, 1.f, 0, 0, 0);

    // exp-scores[nq][nk] = exp(scale * q . k), fp16 out; row sums accumulated atomically
    const dim3 g_ss(NSP/128, NSP/128, BATCH);
    hgemm<<<g_ss, 256, SMEM_BYTES>>>((const __half*)p_qkT, (const __half*)p_qkT + CCH,
                                     nullptr, nullptr, p_rsum, p_attnh,
                                     CCH, 2*CCH, 2*CCH, NSP, sQK, sQK, sAT,
                                     0.04419417382415922f, 0, 0, 1);

    // oT[nq][c] = (1/rsum[nq]) * (expS . v^T)   (M=4096, N=512, K=4096)
    const dim3 g_nq(CCH/128, NSP/128, BATCH);
    hgemm<<<g_nq, 256, SMEM_BYTES>>>((const __half*)p_attnh, (const __half*)p_v,
                                     nullptr, nullptr, p_rsum, p_oT,
                                     NSP, NSP, NSP, CCH, sAT, sNC, sNC, 1.f, 0, 0, 0);

    // out[co][n] = Wo . oT^T + bo + x   (M=512, N=4096, K=512), fp32 out + residual
    hgemm<<<g_cn, 256, SMEM_BYTES>>>(hw + 3*(size_t)WN, (const __half*)p_oT, bo, x, nullptr, out,
                                     CCH, CCH, CCH, NSP, 0, sNC, (size_t)CCH * NSP, 1.f, 0, 1, 0);
}